// round 10
// baseline (speedup 1.0000x reference)
#include <cuda_runtime.h>
#include <cstdint>

#define C_DIM 128
#define K_NB  32
#define MAX_N 100000
#define WP_STRIDE 129   // u64 stride for packed-W smem rows (pad kills STS conflicts)

// Scratch (no-alloc rule: __device__ globals)
__device__ float g_supports[(size_t)MAX_N * C_DIM];

typedef unsigned long long u64;

__device__ __forceinline__ u64 pack2(float lo, float hi) {
    u64 r;
    asm("mov.b64 %0, {%1, %2};" : "=l"(r) : "f"(lo), "f"(hi));
    return r;
}
__device__ __forceinline__ void fma2(u64 &d, u64 a, u64 b) {
    asm("fma.rn.f32x2 %0, %1, %2, %0;" : "+l"(d) : "l"(a), "l"(b));
}
__device__ __forceinline__ float2 unpack2(u64 v) {
    float2 f;
    asm("mov.b64 {%0, %1}, %2;" : "=f"(f.x), "=f"(f.y) : "l"(v));
    return f;
}

// ---------------------------------------------------------------------------
// Kernel 1: supports = leaky_relu(word_vec @ W^T + b, 0.2)
// 128 rows/block, 256 threads. Thread = 16 rows x 4 colgroups, K-packed FFMA2
// (accumulator lanes hold even/odd-c partials, summed at the end).
// Smem: Wp = u64 c-pairs [64][WP_STRIDE] (conflict-free LDS.64 w-loads),
//       xs = float [128][128] (x tile; ulonglong2 broadcast reads; reused
//       as output staging so global stores stay float4-coalesced).
// Per c4-step/warp: 8 LDS.64 + 16 LDS.128-bcast vs 128 FFMA2 -> FFMA2-bound.
// ---------------------------------------------------------------------------
__global__ __launch_bounds__(256, 1) void proj_kernel(
    const float* __restrict__ x,
    const float* __restrict__ W,
    const float* __restrict__ bias,
    float* __restrict__ out,
    int N)
{
    extern __shared__ char smem_raw[];
    u64*   Wp = (u64*)smem_raw;                             // [64][WP_STRIDE]
    float* xs = (float*)(smem_raw + 64 * WP_STRIDE * 8);    // [128][128]

    const int tx  = threadIdx.x;
    const int ty  = threadIdx.y;
    const int tid = ty * 32 + tx;
    const int rowBase = blockIdx.x * 128;

    // Pack W into c-pair u64s: Wp[c2][col] = (W[col][2c2], W[col][2c2+1]).
    #pragma unroll
    for (int i = tid; i < C_DIM * 32; i += 256) {
        int col = i >> 5;
        int c4  = i & 31;
        float4 v = ((const float4*)(W + (size_t)col * C_DIM))[c4];
        Wp[(2 * c4 + 0) * WP_STRIDE + col] = pack2(v.x, v.y);
        Wp[(2 * c4 + 1) * WP_STRIDE + col] = pack2(v.z, v.w);
    }

    // Load 128-row x tile (float4 coalesced, zero-pad tail).
    #pragma unroll
    for (int i = tid; i < 128 * 32; i += 256) {
        int r  = i >> 5;
        int c4 = i & 31;
        int row = rowBase + r;
        float4 v = make_float4(0.f, 0.f, 0.f, 0.f);
        if (row < N) v = ((const float4*)(x + (size_t)row * C_DIM))[c4];
        ((float4*)(xs + r * C_DIM))[c4] = v;
    }
    __syncthreads();

    u64 acc[16][4];
    #pragma unroll
    for (int r = 0; r < 16; r++)
        #pragma unroll
        for (int m = 0; m < 4; m++) acc[r][m] = 0ull;

    const float* xrow = xs + (ty * 16) * C_DIM;

    #pragma unroll 4
    for (int c4 = 0; c4 < 32; c4++) {
        const u64* wa = Wp + (2 * c4 + 0) * WP_STRIDE + tx;
        const u64* wb = Wp + (2 * c4 + 1) * WP_STRIDE + tx;
        u64 w0a = wa[0],  w0b = wb[0];
        u64 w1a = wa[32], w1b = wb[32];
        u64 w2a = wa[64], w2b = wb[64];
        u64 w3a = wa[96], w3b = wb[96];
        #pragma unroll
        for (int r = 0; r < 16; r++) {
            ulonglong2 xv = *(const ulonglong2*)(xrow + r * C_DIM + 4 * c4); // bcast
            fma2(acc[r][0], w0a, xv.x); fma2(acc[r][0], w0b, xv.y);
            fma2(acc[r][1], w1a, xv.x); fma2(acc[r][1], w1b, xv.y);
            fma2(acc[r][2], w2a, xv.x); fma2(acc[r][2], w2b, xv.y);
            fma2(acc[r][3], w3a, xv.x); fma2(acc[r][3], w3b, xv.y);
        }
    }
    __syncthreads();   // done reading xs; reuse as output staging

    float bv[4];
    #pragma unroll
    for (int m = 0; m < 4; m++) bv[m] = bias[tx + 32 * m];

    float* res = xs;   // [128][128]
    #pragma unroll
    for (int r = 0; r < 16; r++) {
        #pragma unroll
        for (int m = 0; m < 4; m++) {
            float2 v = unpack2(acc[r][m]);
            float s = v.x + v.y + bv[m];
            res[(ty * 16 + r) * C_DIM + tx + 32 * m] = s > 0.f ? s : 0.2f * s;
        }
    }
    __syncthreads();

    // Coalesced float4 stores: out is write-once -> streaming (no L2 footprint);
    // g_supports is re-read by att -> default policy.
    #pragma unroll
    for (int i = tid; i < 128 * 32; i += 256) {
        int r  = i >> 5;
        int c4 = i & 31;
        int row = rowBase + r;
        if (row < N) {
            float4 v = ((const float4*)(res + r * C_DIM))[c4];
            __stcs((float4*)(out + (size_t)row * C_DIM) + c4, v);
            ((float4*)(g_supports + (size_t)row * C_DIM))[c4] = v;
        }
    }
}

// ---------------------------------------------------------------------------
// Kernel 2: fused scores -> mask -> softmax -> aggregation -> scatter.
// One block (128 threads = 4 warps) per source s.
// Masked-out neighbors skipped in the dot phase (their softmax weight is
// exactly 0 in fp32, identical to the reference's exp underflow).
// Aggregation: fully-unrolled predicated loop over all 32 k (no branches,
// front-batched MLP). Index/mask reads and out writes use streaming hints so
// wv + g_supports (102MB) stay L2-resident (L2 = 126MB).
// ---------------------------------------------------------------------------
__global__ __launch_bounds__(128) void att_kernel(
    const float* __restrict__ wv,
    const int* __restrict__ src_idx,
    const int* __restrict__ neigh,
    const int* __restrict__ mask,
    float* __restrict__ out,
    int S)
{
    __shared__ float sc[K_NB];
    __shared__ int   nb[K_NB];

    const int s    = blockIdx.x;
    const int tid  = threadIdx.x;
    const int w    = tid >> 5;
    const int lane = tid & 31;
    const int k0   = w * 8;

    const int src = src_idx[s];
    const float4 q = ((const float4*)(wv + (size_t)src * C_DIM))[lane];

    // lanes 0..7 fetch this warp's 8 neighbor indices + masks (streaming)
    int myn = 0, mym = 0;
    if (lane < 8) {
        myn = __ldcs(neigh + (size_t)s * K_NB + k0 + lane);
        mym = __ldcs(mask  + (size_t)s * K_NB + k0 + lane);
        nb[k0 + lane] = myn;
    }

    float p[8];
    int   mk[8];
    #pragma unroll
    for (int kk = 0; kk < 8; kk++) {
        int nk = __shfl_sync(0xffffffffu, myn, kk);
        mk[kk] = __shfl_sync(0xffffffffu, mym, kk);
        if (mk[kk]) {   // warp-uniform branch
            float4 kv = ((const float4*)(wv + (size_t)nk * C_DIM))[lane];
            p[kk] = q.x * kv.x + q.y * kv.y + q.z * kv.z + q.w * kv.w;
        } else {
            p[kk] = 0.f;
        }
    }
    #pragma unroll
    for (int lvl = 16; lvl > 0; lvl >>= 1) {
        #pragma unroll
        for (int kk = 0; kk < 8; kk++)
            p[kk] += __shfl_xor_sync(0xffffffffu, p[kk], lvl);
    }
    if (lane == 0) {
        #pragma unroll
        for (int kk = 0; kk < 8; kk++)
            sc[k0 + kk] = mk[kk] ? p[kk] * 5.0f : -1e6f;
    }
    __syncthreads();

    // warp 0: masked softmax in-place (probs of masked-out k become 0)
    if (tid < 32) {
        float v = sc[tid];
        bool act = (v != -1e6f);
        unsigned bal = __ballot_sync(0xffffffffu, act);
        float pr;
        if (bal == 0) {
            pr = 1.0f / 32.0f;   // all masked -> uniform (matches reference)
        } else {
            float m = v;   // inactive lanes hold -1e6, never win the max
            m = fmaxf(m, __shfl_xor_sync(0xffffffffu, m, 16));
            m = fmaxf(m, __shfl_xor_sync(0xffffffffu, m, 8));
            m = fmaxf(m, __shfl_xor_sync(0xffffffffu, m, 4));
            m = fmaxf(m, __shfl_xor_sync(0xffffffffu, m, 2));
            m = fmaxf(m, __shfl_xor_sync(0xffffffffu, m, 1));
            float e = act ? __expf(v - m) : 0.f;
            float sum = e;
            sum += __shfl_xor_sync(0xffffffffu, sum, 16);
            sum += __shfl_xor_sync(0xffffffffu, sum, 8);
            sum += __shfl_xor_sync(0xffffffffu, sum, 4);
            sum += __shfl_xor_sync(0xffffffffu, sum, 2);
            sum += __shfl_xor_sync(0xffffffffu, sum, 1);
            pr = e / sum;
        }
        sc[tid] = pr;
    }
    __syncthreads();

    // aggregation: all 32 k, predicated on prob != 0 (exact-zero skip matches
    // the reference, where those terms contribute exactly 0).
    const float* sup = g_supports + tid;
    float acc = 0.f;
    #pragma unroll
    for (int j = 0; j < 8; j++) {
        float4 pv = ((const float4*)sc)[j];   // broadcast
        int4   nv = ((const int4*)nb)[j];     // broadcast
        if (pv.x != 0.f) acc = fmaf(pv.x, sup[(size_t)nv.x * C_DIM], acc);
        if (pv.y != 0.f) acc = fmaf(pv.y, sup[(size_t)nv.y * C_DIM], acc);
        if (pv.z != 0.f) acc = fmaf(pv.z, sup[(size_t)nv.z * C_DIM], acc);
        if (pv.w != 0.f) acc = fmaf(pv.w, sup[(size_t)nv.w * C_DIM], acc);
    }
    __stcs(out + (size_t)src * C_DIM + tid, acc);
}

// ---------------------------------------------------------------------------
extern "C" void kernel_launch(void* const* d_in, const int* in_sizes, int n_in,
                              void* d_out, int out_size)
{
    const float* word_vec = (const float*)d_in[0];
    const int*   src_idx  = (const int*)d_in[1];   // int32 from harness
    const int*   neighs   = (const int*)d_in[2];   // int32 from harness
    const int*   src_mask = (const int*)d_in[3];
    const float* W        = (const float*)d_in[4];
    const float* b        = (const float*)d_in[5];
    float*       out      = (float*)d_out;

    const int N = in_sizes[0] / C_DIM;
    const int S = in_sizes[1];

    const int smem_bytes = 64 * WP_STRIDE * 8 + 128 * C_DIM * 4;  // 66048+65536
    cudaFuncSetAttribute(proj_kernel,
                         cudaFuncAttributeMaxDynamicSharedMemorySize, smem_bytes);

    dim3 blk(32, 8);
    proj_kernel<<<(N + 127) / 128, blk, smem_bytes>>>(word_vec, W, b, out, N);

    att_kernel<<<S, 128>>>(word_vec, src_idx, neighs, src_mask, out, S);
}